// round 13
// baseline (speedup 1.0000x reference)
#include <cuda_runtime.h>

// Fixed problem shape
#define BB   2048
#define TTN  2048
#define HH   51
#define RPB  16          // batch rows per block (2 groups x 8 rows)
#define NBLK 128
#define NTHR 256
#define HCW  12          // hcat row width in floats (8 rows + pad)

typedef unsigned long long u64;

__device__ __forceinline__ u64 pk2(float a) {
    u64 r; asm("mov.b64 %0, {%1, %1};" : "=l"(r) : "f"(a)); return r;
}
__device__ __forceinline__ u64 fma2(u64 a, u64 b, u64 c) {
    u64 d; asm("fma.rn.f32x2 %0, %1, %2, %3;" : "=l"(d) : "l"(a), "l"(b), "l"(c)); return d;
}
union U2 { u64 v; float2 f; };

__device__ __forceinline__ float tanhap(float x) {
    float y; asm("tanh.approx.f32 %0, %1;" : "=f"(y) : "f"(x)); return y;
}
__device__ __forceinline__ float sigap(float x) {
    return fmaf(0.5f, tanhap(0.5f * x), 0.5f);
}
__device__ __forceinline__ float cellstep(float gi, float gf, float gg, float go, float& c) {
    float cn = sigap(gf) * c + sigap(gi) * tanhap(gg);
    c = cn;
    return sigap(go) * tanhap(cn);
}

#define GBAR(id) asm volatile("bar.sync %0, 128;" :: "r"(id) : "memory")

// ---------------- smem layout (float offsets) ----------------
// W1s : [k 0..51][u*4+g] row 208; k<51 = Whh1[:,k], k=51 = Wih1 (x weight)
// W2s : [k 0..102][u*4+g]; k<51 = Wih2[:,k], k=51 = 0 (x slot), 52..102 = Whh2[:,k-52]
// hcatP/hcatQ : per-group [k 0..102][row 0..7 pad 12]; k: 0..50 h1_t, 51 x_{t+1}, 52..102 h2_{t-1}
#define W1S_OFF 0                        // 52*208 = 10816
#define W2S_OFF 10816                    // 103*208 = 21424
#define BS1_OFF 32240                    // 208
#define BS2_OFF 32448                    // 208
#define WLS_OFF 32656                    // 64
#define HCP_OFF 32720                    // 103*12 = 1236  (byte ofs 130880, 16B aligned)
#define HCQ_OFF 33956                    // 1236           (byte ofs 135824, 16B aligned)
#define SM_TOT  35192                    // 140,768 B

__global__ __launch_bounds__(NTHR, 1)
void lstm2_kernel(const float* __restrict__ input,
                  const float* __restrict__ Wih1, const float* __restrict__ Whh1,
                  const float* __restrict__ bih1, const float* __restrict__ bhh1,
                  const float* __restrict__ Wih2, const float* __restrict__ Whh2,
                  const float* __restrict__ bih2, const float* __restrict__ bhh2,
                  const float* __restrict__ Wlin, const float* __restrict__ blin,
                  float* __restrict__ out)
{
    extern __shared__ float sm[];
    const int tid = threadIdx.x;

    float* bs1 = sm + BS1_OFF;
    float* bs2 = sm + BS2_OFF;
    float* wls = sm + WLS_OFF;
    const float4* W1s4 = reinterpret_cast<const float4*>(sm + W1S_OFF);
    const float4* W2s4 = reinterpret_cast<const float4*>(sm + W2S_OFF);

    // ---------------- staging (all 256 threads) ----------------
    for (int q = tid; q < 52 * 204; q += NTHR) {
        int k = q / 204, c = q % 204;
        int uu = c >> 2, g = c & 3, j = g * HH + uu;
        sm[W1S_OFF + k * 208 + c] = (k < HH) ? Whh1[j * HH + k] : Wih1[j];
    }
    for (int q = tid; q < 103 * 204; q += NTHR) {
        int k = q / 204, c = q % 204;
        int uu = c >> 2, g = c & 3, j = g * HH + uu;
        float v;
        if (k < HH)       v = Wih2[j * HH + k];
        else if (k == HH) v = 0.0f;
        else              v = Whh2[j * HH + (k - 52)];
        sm[W2S_OFF + k * 208 + c] = v;
    }
    for (int c = tid; c < 208; c += NTHR) {
        if (c < 204) {
            int uu = c >> 2, g = c & 3, j = g * HH + uu;
            bs1[c] = bih1[j] + bhh1[j];
            bs2[c] = bih2[j] + bhh2[j];
        } else { bs1[c] = 0.f; bs2[c] = 0.f; }
    }
    if (tid < HH) wls[tid] = Wlin[tid];
    for (int i = tid; i < 2 * 103 * HCW; i += NTHR) sm[HCP_OFF + i] = 0.0f;
    __syncthreads();

    // ---------------- group split: warps 0-3 = P (rows 0-7), warps 4-7 = Q (rows 8-15) ----------------
    const int grp  = tid >> 7;            // 0 or 1
    const int lt   = tid & 127;
    const int bid  = grp + 1;             // named barrier id 1 / 2
    float* hcf = sm + (grp ? HCQ_OFF : HCP_OFF);
    const int rowg = blockIdx.x * RPB + grp * 8;

    // roles within group
    const bool cw = (lt < 102);
    const int  u = lt >> 1, rh = lt & 1, rbase = rh * 4;   // unit u, 4 rows rbase..rbase+3
    const bool yw = (lt >= 102 && lt < 110);
    const int  yr = lt - 102;
    const bool xw = (lt >= 110 && lt < 114);
    const int  xi = lt - 110;

    // x_0 into slot k=51
    if (lt < 8) hcf[51 * HCW + lt] = __ldg(&input[(rowg + lt) * TTN]);
    GBAR(bid);

    float c1s[4] = {0,0,0,0};
    float c2s[4] = {0,0,0,0};
    U2 a1[4][2], a2[4][2];                 // [gate][rowpair]
    float bf1[4] = {0,0,0,0}, bf2[4] = {0,0,0,0};
    if (cw) {
        #pragma unroll
        for (int g = 0; g < 4; g++) { bf1[g] = bs1[u * 4 + g]; bf2[g] = bs2[u * 4 + g]; }
    }
    const float ybias = blin[0];

    float2 xa = make_float2(0.f, 0.f);     // x_{t+1} prefetch (2 rows per x-thread)
    if (xw) xa = make_float2(__ldg(&input[(rowg + 2 * xi) * TTN + 1]),
                             __ldg(&input[(rowg + 2 * xi + 1) * TTN + 1]));

    #define SHARED_K(kv)                                                                   \
        {                                                                                   \
            float4 w1 = W1s4[(kv) * 52 + u];                                                \
            float4 w2 = W2s4[(kv) * 52 + u];                                                \
            ulonglong2 hv = *reinterpret_cast<const ulonglong2*>(&hcf[(kv) * HCW + rbase]); \
            u64 wg;                                                                         \
            wg = pk2(w1.x); a1[0][0].v = fma2(wg, hv.x, a1[0][0].v); a1[0][1].v = fma2(wg, hv.y, a1[0][1].v); \
            wg = pk2(w1.y); a1[1][0].v = fma2(wg, hv.x, a1[1][0].v); a1[1][1].v = fma2(wg, hv.y, a1[1][1].v); \
            wg = pk2(w1.z); a1[2][0].v = fma2(wg, hv.x, a1[2][0].v); a1[2][1].v = fma2(wg, hv.y, a1[2][1].v); \
            wg = pk2(w1.w); a1[3][0].v = fma2(wg, hv.x, a1[3][0].v); a1[3][1].v = fma2(wg, hv.y, a1[3][1].v); \
            wg = pk2(w2.x); a2[0][0].v = fma2(wg, hv.x, a2[0][0].v); a2[0][1].v = fma2(wg, hv.y, a2[0][1].v); \
            wg = pk2(w2.y); a2[1][0].v = fma2(wg, hv.x, a2[1][0].v); a2[1][1].v = fma2(wg, hv.y, a2[1][1].v); \
            wg = pk2(w2.z); a2[2][0].v = fma2(wg, hv.x, a2[2][0].v); a2[2][1].v = fma2(wg, hv.y, a2[2][1].v); \
            wg = pk2(w2.w); a2[3][0].v = fma2(wg, hv.x, a2[3][0].v); a2[3][1].v = fma2(wg, hv.y, a2[3][1].v); \
        }

    #define W2ONLY_K(kv)                                                                   \
        {                                                                                   \
            float4 w2 = W2s4[(kv) * 52 + u];                                                \
            ulonglong2 hv = *reinterpret_cast<const ulonglong2*>(&hcf[(kv) * HCW + rbase]); \
            u64 wg;                                                                         \
            wg = pk2(w2.x); a2[0][0].v = fma2(wg, hv.x, a2[0][0].v); a2[0][1].v = fma2(wg, hv.y, a2[0][1].v); \
            wg = pk2(w2.y); a2[1][0].v = fma2(wg, hv.x, a2[1][0].v); a2[1][1].v = fma2(wg, hv.y, a2[1][1].v); \
            wg = pk2(w2.z); a2[2][0].v = fma2(wg, hv.x, a2[2][0].v); a2[2][1].v = fma2(wg, hv.y, a2[2][1].v); \
            wg = pk2(w2.w); a2[3][0].v = fma2(wg, hv.x, a2[3][0].v); a2[3][1].v = fma2(wg, hv.y, a2[3][1].v); \
        }

    // ---------------- prolog: L1 gates for t=0 (h1=0, x_0) ----------------
    if (cw) {
        #pragma unroll
        for (int g = 0; g < 4; g++) {
            u64 b1 = pk2(bf1[g]); a1[g][0].v = b1; a1[g][1].v = b1;
            a2[g][0].v = 0ull; a2[g][1].v = 0ull;
        }
        #pragma unroll 4
        for (int k = 0; k < 52; k++) SHARED_K(k)
    }
    GBAR(bid);

    // ---------------- main loop: 2 group-barriers/step ----------------
    for (int t = 0; t < TTN; t++) {
        // === ACT: a1 -> h1_t; a2 -> h2_{t-1}; publish x_{t+1} ===
        if (cw) {
            float4 h1n;
            {
                float2 gi = a1[0][0].f, gf = a1[1][0].f, gg = a1[2][0].f, go = a1[3][0].f;
                h1n.x = cellstep(gi.x, gf.x, gg.x, go.x, c1s[0]);
                h1n.y = cellstep(gi.y, gf.y, gg.y, go.y, c1s[1]);
                gi = a1[0][1].f; gf = a1[1][1].f; gg = a1[2][1].f; go = a1[3][1].f;
                h1n.z = cellstep(gi.x, gf.x, gg.x, go.x, c1s[2]);
                h1n.w = cellstep(gi.y, gf.y, gg.y, go.y, c1s[3]);
            }
            *reinterpret_cast<float4*>(&hcf[u * HCW + rbase]) = h1n;
            if (t > 0) {
                float4 h2n;
                float2 gi = a2[0][0].f, gf = a2[1][0].f, gg = a2[2][0].f, go = a2[3][0].f;
                h2n.x = cellstep(gi.x, gf.x, gg.x, go.x, c2s[0]);
                h2n.y = cellstep(gi.y, gf.y, gg.y, go.y, c2s[1]);
                gi = a2[0][1].f; gf = a2[1][1].f; gg = a2[2][1].f; go = a2[3][1].f;
                h2n.z = cellstep(gi.x, gf.x, gg.x, go.x, c2s[2]);
                h2n.w = cellstep(gi.y, gf.y, gg.y, go.y, c2s[3]);
                *reinterpret_cast<float4*>(&hcf[(52 + u) * HCW + rbase]) = h2n;
            }
        } else if (xw && t + 1 < TTN) {
            hcf[51 * HCW + 2 * xi]     = xa.x;          // publish x_{t+1}
            hcf[51 * HCW + 2 * xi + 1] = xa.y;
            if (t + 2 < TTN)
                xa = make_float2(__ldg(&input[(rowg + 2 * xi) * TTN + t + 2]),
                                 __ldg(&input[(rowg + 2 * xi + 1) * TTN + t + 2]));
        }
        GBAR(bid);

        // === GEMM: a2 = W2*[h1_t | h2_{t-1}]; a1 = W1*[h1_t | x_{t+1}]; y_{t-1} ===
        if (cw) {
            #pragma unroll
            for (int g = 0; g < 4; g++) {
                u64 b1 = pk2(bf1[g]); a1[g][0].v = b1; a1[g][1].v = b1;
                u64 b2 = pk2(bf2[g]); a2[g][0].v = b2; a2[g][1].v = b2;
            }
            #pragma unroll 4
            for (int k = 0; k < 52; k++) SHARED_K(k)       // h1 + x slot
            #pragma unroll 4
            for (int k = 52; k < 103; k++) W2ONLY_K(k)     // h2_{t-1}
        } else if (yw && t > 0) {
            float y = ybias;                                // y_{t-1} from stable h2 region
            #pragma unroll 3
            for (int k = 0; k < HH; k++)
                y += hcf[(52 + k) * HCW + yr] * wls[k];
            out[(rowg + yr) * TTN + (t - 1)] = y;
        }
        GBAR(bid);
    }

    // ---------------- epilog: act2 for t=TTN-1, then y_{TTN-1} ----------------
    if (cw) {
        float4 h2n;
        float2 gi = a2[0][0].f, gf = a2[1][0].f, gg = a2[2][0].f, go = a2[3][0].f;
        h2n.x = cellstep(gi.x, gf.x, gg.x, go.x, c2s[0]);
        h2n.y = cellstep(gi.y, gf.y, gg.y, go.y, c2s[1]);
        gi = a2[0][1].f; gf = a2[1][1].f; gg = a2[2][1].f; go = a2[3][1].f;
        h2n.z = cellstep(gi.x, gf.x, gg.x, go.x, c2s[2]);
        h2n.w = cellstep(gi.y, gf.y, gg.y, go.y, c2s[3]);
        *reinterpret_cast<float4*>(&hcf[(52 + u) * HCW + rbase]) = h2n;
    }
    GBAR(bid);
    if (yw) {
        float y = ybias;
        #pragma unroll 3
        for (int k = 0; k < HH; k++)
            y += hcf[(52 + k) * HCW + yr] * wls[k];
        out[(rowg + yr) * TTN + (TTN - 1)] = y;
    }
}

extern "C" void kernel_launch(void* const* d_in, const int* in_sizes, int n_in,
                              void* d_out, int out_size) {
    const float* input = (const float*)d_in[0];
    const float* Wih1  = (const float*)d_in[1];
    const float* Whh1  = (const float*)d_in[2];
    const float* bih1  = (const float*)d_in[3];
    const float* bhh1  = (const float*)d_in[4];
    const float* Wih2  = (const float*)d_in[5];
    const float* Whh2  = (const float*)d_in[6];
    const float* bih2  = (const float*)d_in[7];
    const float* bhh2  = (const float*)d_in[8];
    const float* Wlin  = (const float*)d_in[9];
    const float* blin  = (const float*)d_in[10];
    float* out = (float*)d_out;

    const size_t smem = SM_TOT * sizeof(float);   // ~141 KB
    cudaFuncSetAttribute(lstm2_kernel, cudaFuncAttributeMaxDynamicSharedMemorySize, (int)smem);

    lstm2_kernel<<<NBLK, NTHR, smem>>>(input, Wih1, Whh1, bih1, bhh1,
                                       Wih2, Whh2, bih2, bhh2, Wlin, blin, out);
}

// round 14
// speedup vs baseline: 1.3540x; 1.3540x over previous
#include <cuda_runtime.h>

// Fixed problem shape
#define BB   2048
#define TTN  2048
#define HH   51
#define RPB  16          // batch rows per block
#define NBLK 128
#define NTHR 128
#define GT   102         // gate threads: u=tid>>1 (0..50), rh=tid&1 (8 rows each)

typedef unsigned long long u64;

__device__ __forceinline__ u64 fma2(u64 a, u64 b, u64 c) {
    u64 d; asm("fma.rn.f32x2 %0, %1, %2, %3;" : "=l"(d) : "l"(a), "l"(b), "l"(c)); return d;
}
union U2 { u64 v; float2 f; };

__device__ __forceinline__ float tanhap(float x) {
    float y; asm("tanh.approx.f32 %0, %1;" : "=f"(y) : "f"(x)); return y;
}
__device__ __forceinline__ float sigap(float x) {
    return fmaf(0.5f, tanhap(0.5f * x), 0.5f);
}
__device__ __forceinline__ float cellstep(float gi, float gf, float gg, float go, float& c) {
    float cn = sigap(gf) * c + sigap(gi) * tanhap(gg);
    c = cn;
    return sigap(go) * tanhap(cn);
}

// ---------------- smem layout (float offsets) ----------------
// W1s : [k 0..51][u*4+g] row 208; k<51 = Whh1[:,k], k=51 = Wih1 (x weight)
//       gate order i,f,g,o -> natural u64 pairs (w_i,w_f),(w_g,w_o)
// W2s : [k 0..102][u*4+g]; k<51 = Wih2[:,k], k=51 = 0 (x slot), 52..102 = Whh2[:,k-52]
// hdup: [k 0..102][row 0..15] DUPLICATED pairs (h,h) -> 32 floats/k
//       k: 0..50 h1_t, 51 x_{t+1}, 52..102 h2_{t-1}
// bs1/bs2: combined biases in u*4+g order (pairs load directly)
#define W1S_OFF 0                        // 52*208 = 10816
#define W2S_OFF 10816                    // 103*208 = 21424
#define HD_OFF  32240                    // 103*32 = 3296 (byte ofs 128960, 16B aligned)
#define BS1_OFF 35536                    // 208
#define BS2_OFF 35744                    // 208
#define WLS_OFF 35952                    // 64
#define SM_TOT  36016                    // 144,064 B

__global__ __launch_bounds__(NTHR, 1)
void lstm2_kernel(const float* __restrict__ input,
                  const float* __restrict__ Wih1, const float* __restrict__ Whh1,
                  const float* __restrict__ bih1, const float* __restrict__ bhh1,
                  const float* __restrict__ Wih2, const float* __restrict__ Whh2,
                  const float* __restrict__ bih2, const float* __restrict__ bhh2,
                  const float* __restrict__ Wlin, const float* __restrict__ blin,
                  float* __restrict__ out)
{
    extern __shared__ float sm[];
    const int tid  = threadIdx.x;
    const int row0 = blockIdx.x * RPB;

    float* W1f  = sm + W1S_OFF;
    float* W2f  = sm + W2S_OFF;
    float* hdf  = sm + HD_OFF;
    float* bs1  = sm + BS1_OFF;
    float* bs2  = sm + BS2_OFF;
    float* wls  = sm + WLS_OFF;

    // ---------------- staging ----------------
    for (int q = tid; q < 52 * 204; q += NTHR) {
        int k = q / 204, c = q % 204;
        int uu = c >> 2, g = c & 3, j = g * HH + uu;
        W1f[k * 208 + c] = (k < HH) ? Whh1[j * HH + k] : Wih1[j];
    }
    for (int q = tid; q < 103 * 204; q += NTHR) {
        int k = q / 204, c = q % 204;
        int uu = c >> 2, g = c & 3, j = g * HH + uu;
        float v;
        if (k < HH)       v = Wih2[j * HH + k];
        else if (k == HH) v = 0.0f;
        else              v = Whh2[j * HH + (k - 52)];
        W2f[k * 208 + c] = v;
    }
    for (int c = tid; c < 208; c += NTHR) {
        if (c < 204) {
            int uu = c >> 2, g = c & 3, j = g * HH + uu;
            bs1[c] = bih1[j] + bhh1[j];
            bs2[c] = bih2[j] + bhh2[j];
        } else { bs1[c] = 0.f; bs2[c] = 0.f; }
    }
    if (tid < HH) wls[tid] = Wlin[tid];
    for (int i = tid; i < 103 * 32; i += NTHR) hdf[i] = 0.0f;
    __syncthreads();
    if (tid < RPB) {                       // x_0 duplicated into slot k=51
        float v = __ldg(&input[(row0 + tid) * TTN]);
        *reinterpret_cast<float2*>(&hdf[51 * 32 + 2 * tid]) = make_float2(v, v);
    }
    __syncthreads();

    // ---------------- roles ----------------
    const bool cw = (tid < GT);
    const int  u = tid >> 1, rh = tid & 1;
    const int  hofs = rh * 16;             // float offset of this thread's 8 dup-pairs
    const bool yw = (tid >= 102 && tid < 118);
    const int  yr = tid - 102;
    const bool xw = (tid >= 118 && tid < 126);
    const int  xi = tid - 118;

    float c1s[8] = {0,0,0,0,0,0,0,0};
    float c2s[8] = {0,0,0,0,0,0,0,0};
    U2 a1[2][8], a2[2][8];                 // [gatepair][row]: lo=gate i/g, hi=gate f/o
    const float ybias = blin[0];

    float2 xa = make_float2(0.f, 0.f);     // x_{t+1} prefetch (2 rows per x-thread)
    if (xw) xa = make_float2(__ldg(&input[(row0 + 2 * xi) * TTN + 1]),
                             __ldg(&input[(row0 + 2 * xi + 1) * TTN + 1]));

    // zero-MOV inner iterations: weight pairs + dup-h pairs straight from smem
    #define SHARED_K(kv)                                                                    \
        {                                                                                    \
            ulonglong2 w1v = *reinterpret_cast<const ulonglong2*>(&W1f[(kv) * 208 + u * 4]); \
            ulonglong2 w2v = *reinterpret_cast<const ulonglong2*>(&W2f[(kv) * 208 + u * 4]); \
            const ulonglong2* hp = reinterpret_cast<const ulonglong2*>(&hdf[(kv) * 32 + hofs]); \
            ulonglong2 hA = hp[0], hB = hp[1], hC = hp[2], hD = hp[3];                       \
            a1[0][0].v = fma2(w1v.x, hA.x, a1[0][0].v); a1[1][0].v = fma2(w1v.y, hA.x, a1[1][0].v); \
            a1[0][1].v = fma2(w1v.x, hA.y, a1[0][1].v); a1[1][1].v = fma2(w1v.y, hA.y, a1[1][1].v); \
            a1[0][2].v = fma2(w1v.x, hB.x, a1[0][2].v); a1[1][2].v = fma2(w1v.y, hB.x, a1[1][2].v); \
            a1[0][3].v = fma2(w1v.x, hB.y, a1[0][3].v); a1[1][3].v = fma2(w1v.y, hB.y, a1[1][3].v); \
            a1[0][4].v = fma2(w1v.x, hC.x, a1[0][4].v); a1[1][4].v = fma2(w1v.y, hC.x, a1[1][4].v); \
            a1[0][5].v = fma2(w1v.x, hC.y, a1[0][5].v); a1[1][5].v = fma2(w1v.y, hC.y, a1[1][5].v); \
            a1[0][6].v = fma2(w1v.x, hD.x, a1[0][6].v); a1[1][6].v = fma2(w1v.y, hD.x, a1[1][6].v); \
            a1[0][7].v = fma2(w1v.x, hD.y, a1[0][7].v); a1[1][7].v = fma2(w1v.y, hD.y, a1[1][7].v); \
            a2[0][0].v = fma2(w2v.x, hA.x, a2[0][0].v); a2[1][0].v = fma2(w2v.y, hA.x, a2[1][0].v); \
            a2[0][1].v = fma2(w2v.x, hA.y, a2[0][1].v); a2[1][1].v = fma2(w2v.y, hA.y, a2[1][1].v); \
            a2[0][2].v = fma2(w2v.x, hB.x, a2[0][2].v); a2[1][2].v = fma2(w2v.y, hB.x, a2[1][2].v); \
            a2[0][3].v = fma2(w2v.x, hB.y, a2[0][3].v); a2[1][3].v = fma2(w2v.y, hB.y, a2[1][3].v); \
            a2[0][4].v = fma2(w2v.x, hC.x, a2[0][4].v); a2[1][4].v = fma2(w2v.y, hC.x, a2[1][4].v); \
            a2[0][5].v = fma2(w2v.x, hC.y, a2[0][5].v); a2[1][5].v = fma2(w2v.y, hC.y, a2[1][5].v); \
            a2[0][6].v = fma2(w2v.x, hD.x, a2[0][6].v); a2[1][6].v = fma2(w2v.y, hD.x, a2[1][6].v); \
            a2[0][7].v = fma2(w2v.x, hD.y, a2[0][7].v); a2[1][7].v = fma2(w2v.y, hD.y, a2[1][7].v); \
        }

    #define W2ONLY_K(kv)                                                                    \
        {                                                                                    \
            ulonglong2 w2v = *reinterpret_cast<const ulonglong2*>(&W2f[(kv) * 208 + u * 4]); \
            const ulonglong2* hp = reinterpret_cast<const ulonglong2*>(&hdf[(kv) * 32 + hofs]); \
            ulonglong2 hA = hp[0], hB = hp[1], hC = hp[2], hD = hp[3];                       \
            a2[0][0].v = fma2(w2v.x, hA.x, a2[0][0].v); a2[1][0].v = fma2(w2v.y, hA.x, a2[1][0].v); \
            a2[0][1].v = fma2(w2v.x, hA.y, a2[0][1].v); a2[1][1].v = fma2(w2v.y, hA.y, a2[1][1].v); \
            a2[0][2].v = fma2(w2v.x, hB.x, a2[0][2].v); a2[1][2].v = fma2(w2v.y, hB.x, a2[1][2].v); \
            a2[0][3].v = fma2(w2v.x, hB.y, a2[0][3].v); a2[1][3].v = fma2(w2v.y, hB.y, a2[1][3].v); \
            a2[0][4].v = fma2(w2v.x, hC.x, a2[0][4].v); a2[1][4].v = fma2(w2v.y, hC.x, a2[1][4].v); \
            a2[0][5].v = fma2(w2v.x, hC.y, a2[0][5].v); a2[1][5].v = fma2(w2v.y, hC.y, a2[1][5].v); \
            a2[0][6].v = fma2(w2v.x, hD.x, a2[0][6].v); a2[1][6].v = fma2(w2v.y, hD.x, a2[1][6].v); \
            a2[0][7].v = fma2(w2v.x, hD.y, a2[0][7].v); a2[1][7].v = fma2(w2v.y, hD.y, a2[1][7].v); \
        }

    // ---------------- prolog: L1 gates for t=0 (h1=0, x_0) ----------------
    if (cw) {
        ulonglong2 b1v = *reinterpret_cast<const ulonglong2*>(&bs1[u * 4]);
        #pragma unroll
        for (int r = 0; r < 8; r++) {
            a1[0][r].v = b1v.x; a1[1][r].v = b1v.y;
            a2[0][r].v = 0ull;  a2[1][r].v = 0ull;
        }
        #pragma unroll 4
        for (int k = 0; k < 52; k++) SHARED_K(k)
    }
    __syncthreads();

    // ---------------- main loop: 2 barriers/step ----------------
    for (int t = 0; t < TTN; t++) {
        // === ACT: a1 -> h1_t (dup); a2 -> h2_{t-1} (dup); publish x_{t+1} ===
        if (cw) {
            float h1n[8];
            #pragma unroll
            for (int r = 0; r < 8; r++)
                h1n[r] = cellstep(a1[0][r].f.x, a1[0][r].f.y, a1[1][r].f.x, a1[1][r].f.y, c1s[r]);
            #pragma unroll
            for (int j = 0; j < 4; j++)
                *reinterpret_cast<float4*>(&hdf[u * 32 + hofs + 4 * j]) =
                    make_float4(h1n[2*j], h1n[2*j], h1n[2*j+1], h1n[2*j+1]);
            if (t > 0) {
                float h2n[8];
                #pragma unroll
                for (int r = 0; r < 8; r++)
                    h2n[r] = cellstep(a2[0][r].f.x, a2[0][r].f.y, a2[1][r].f.x, a2[1][r].f.y, c2s[r]);
                #pragma unroll
                for (int j = 0; j < 4; j++)
                    *reinterpret_cast<float4*>(&hdf[(52 + u) * 32 + hofs + 4 * j]) =
                        make_float4(h2n[2*j], h2n[2*j], h2n[2*j+1], h2n[2*j+1]);
            }
        } else if (xw && t + 1 < TTN) {
            *reinterpret_cast<float4*>(&hdf[51 * 32 + 4 * xi]) =
                make_float4(xa.x, xa.x, xa.y, xa.y);            // x_{t+1} dup
            if (t + 2 < TTN)
                xa = make_float2(__ldg(&input[(row0 + 2 * xi) * TTN + t + 2]),
                                 __ldg(&input[(row0 + 2 * xi + 1) * TTN + t + 2]));
        }
        __syncthreads();

        // === GEMM: a2 = W2*[h1_t | h2_{t-1}]; a1 = W1*[h1_t | x_{t+1}]; y_{t-1} ===
        if (cw) {
            ulonglong2 b1v = *reinterpret_cast<const ulonglong2*>(&bs1[u * 4]);
            ulonglong2 b2v = *reinterpret_cast<const ulonglong2*>(&bs2[u * 4]);
            #pragma unroll
            for (int r = 0; r < 8; r++) {
                a1[0][r].v = b1v.x; a1[1][r].v = b1v.y;
                a2[0][r].v = b2v.x; a2[1][r].v = b2v.y;
            }
            #pragma unroll 4
            for (int k = 0; k < 52; k++) SHARED_K(k)       // h1 + x slot
            #pragma unroll 4
            for (int k = 52; k < 103; k++) W2ONLY_K(k)     // h2_{t-1}
        } else if (yw && t > 0) {
            float y = ybias;                                // y_{t-1} from stable h2 region
            #pragma unroll 3
            for (int k = 0; k < HH; k++)
                y += hdf[(52 + k) * 32 + 2 * yr] * wls[k];
            out[(row0 + yr) * TTN + (t - 1)] = y;
        }
        __syncthreads();
    }

    // ---------------- epilog: act2 for t=TTN-1, then y_{TTN-1} ----------------
    if (cw) {
        float h2n[8];
        #pragma unroll
        for (int r = 0; r < 8; r++)
            h2n[r] = cellstep(a2[0][r].f.x, a2[0][r].f.y, a2[1][r].f.x, a2[1][r].f.y, c2s[r]);
        #pragma unroll
        for (int j = 0; j < 4; j++)
            *reinterpret_cast<float4*>(&hdf[(52 + u) * 32 + hofs + 4 * j]) =
                make_float4(h2n[2*j], h2n[2*j], h2n[2*j+1], h2n[2*j+1]);
    }
    __syncthreads();
    if (yw) {
        float y = ybias;
        #pragma unroll 3
        for (int k = 0; k < HH; k++)
            y += hdf[(52 + k) * 32 + 2 * yr] * wls[k];
        out[(row0 + yr) * TTN + (TTN - 1)] = y;
    }
}

extern "C" void kernel_launch(void* const* d_in, const int* in_sizes, int n_in,
                              void* d_out, int out_size) {
    const float* input = (const float*)d_in[0];
    const float* Wih1  = (const float*)d_in[1];
    const float* Whh1  = (const float*)d_in[2];
    const float* bih1  = (const float*)d_in[3];
    const float* bhh1  = (const float*)d_in[4];
    const float* Wih2  = (const float*)d_in[5];
    const float* Whh2  = (const float*)d_in[6];
    const float* bih2  = (const float*)d_in[7];
    const float* bhh2  = (const float*)d_in[8];
    const float* Wlin  = (const float*)d_in[9];
    const float* blin  = (const float*)d_in[10];
    float* out = (float*)d_out;

    const size_t smem = SM_TOT * sizeof(float);   // ~144 KB
    cudaFuncSetAttribute(lstm2_kernel, cudaFuncAttributeMaxDynamicSharedMemorySize, (int)smem);

    lstm2_kernel<<<NBLK, NTHR, smem>>>(input, Wih1, Whh1, bih1, bhh1,
                                       Wih2, Whh2, bih2, bhh2, Wlin, blin, out);
}